// round 13
// baseline (speedup 1.0000x reference)
#include <cuda_runtime.h>

// SpikeLayer LIF scan: x [B=64, T=8, C=256, H=32, W=32] f32 -> spikes, same shape.
// mem = mem*0.25 + x; spike = (mem - 0.5) > 0; mem = (1-spike)*mem.
//
// FINAL (converged at HBM ceiling, verified over 8 independent runs at
// 150.0-150.8us kernel / 157.76-157.98us bench):
//   - one thread = 4 neurons (one float4) across all 8 timesteps
//   - LIF recurrence entirely in registers (no spills, regs=32)
//   - front-batched MLP=8 fully-coalesced LDG.128 hides DRAM latency
//   - default cache ops; flat 2D grid (y = batch); 512-thread CTAs
//   - 32-bit index math (CHW4 = 2^16: shifts only)
//
// Lever matrix (R1-R12): cache hints / persistent grid-stride / MLP=16 /
// CTA 256 vs 512 / fused vs trailing stores / occupancy 54-85% -- all neutral
// or regressions. Every well-formed variant lands at 6.78-6.80 TB/s = 85% of
// 8 TB/s spec with traffic pinned exactly at the 1 GiB floor (512 MiB f32 in
// + 512 MiB f32 spikes out, incompressible given output dtype). Residual gap
// to spec is DRAM refresh + read/write bus turnaround on a 50/50 mixed
// stream -- not addressable from the kernel.

#define LIF_T 8
#define VTH 0.5f
#define DECAY 0.25f
#define CHW4 65536u                  // C*H*W/4 float4 vectors per (b,t) slice
#define BSTRIDE (CHW4 * 8u)          // float4 vectors per batch sample
#define TPB 512u

__global__ __launch_bounds__(TPB) void lif_scan_kernel(
    const float4* __restrict__ x, float4* __restrict__ out)
{
    unsigned n    = blockIdx.x * TPB + threadIdx.x;    // [0, CHW4)
    unsigned base = blockIdx.y * BSTRIDE + n;

    float4 v[LIF_T];
    // Front-batched independent loads: MLP = 8 LDG.128
    #pragma unroll
    for (int t = 0; t < LIF_T; t++)
        v[t] = x[base + (unsigned)t * CHW4];

    float mx = 0.f, my = 0.f, mz = 0.f, mw = 0.f;
    #pragma unroll
    for (int t = 0; t < LIF_T; t++) {
        mx = fmaf(mx, DECAY, v[t].x);
        my = fmaf(my, DECAY, v[t].y);
        mz = fmaf(mz, DECAY, v[t].z);
        mw = fmaf(mw, DECAY, v[t].w);
        float sx = (mx > VTH) ? 1.f : 0.f;
        float sy = (my > VTH) ? 1.f : 0.f;
        float sz = (mz > VTH) ? 1.f : 0.f;
        float sw = (mw > VTH) ? 1.f : 0.f;
        // hard reset where spiked
        mx = (sx != 0.f) ? 0.f : mx;
        my = (sy != 0.f) ? 0.f : my;
        mz = (sz != 0.f) ? 0.f : mz;
        mw = (sw != 0.f) ? 0.f : mw;
        // store this timestep's spikes (ptxas schedules STGs optimally)
        float4 s; s.x = sx; s.y = sy; s.z = sz; s.w = sw;
        out[base + (unsigned)t * CHW4] = s;
    }
}

extern "C" void kernel_launch(void* const* d_in, const int* in_sizes, int n_in,
                              void* d_out, int out_size)
{
    const float4* x = (const float4*)d_in[0];
    float4* out = (float4*)d_out;

    unsigned total   = (unsigned)in_sizes[0];          // B*T*C*H*W
    unsigned batches = total / (LIF_T * CHW4 * 4u);    // = 64 for bench shape

    dim3 grid(CHW4 / TPB, batches, 1);                 // (128, 64) = 8192 CTAs
    lif_scan_kernel<<<grid, TPB>>>(x, out);
}

// round 14
// speedup vs baseline: 1.0026x; 1.0026x over previous
#include <cuda_runtime.h>

// SpikeLayer LIF scan: x [B=64, T=8, C=256, H=32, W=32] f32 -> spikes, same shape.
// mem = mem*0.25 + x; spike = (mem - 0.5) > 0; mem = (1-spike)*mem.
//
// R14 experiment on the converged config: one __syncthreads() between the
// front-batched load phase and the compute+store phase. Aligns all 512
// threads of a CTA so the SM presents a coherent 64KB read burst followed by
// a 64KB write burst to the LTS/DRAM, testing whether coarser read/write
// phasing reduces DRAM bus-turnaround overhead (the verified limiter:
// 9 runs pinned at 6.76-6.80 TB/s = 85% of spec with traffic at the 1 GiB
// incompressible floor). All other parameters identical to the best kernel
// (one thread = 1 float4 x 8 timesteps, regs=32, flat 2D grid, TPB=512,
// default cache ops, 32-bit indexing).

#define LIF_T 8
#define VTH 0.5f
#define DECAY 0.25f
#define CHW4 65536u                  // C*H*W/4 float4 vectors per (b,t) slice
#define BSTRIDE (CHW4 * 8u)          // float4 vectors per batch sample
#define TPB 512u

__global__ __launch_bounds__(TPB) void lif_scan_kernel(
    const float4* __restrict__ x, float4* __restrict__ out)
{
    unsigned n    = blockIdx.x * TPB + threadIdx.x;    // [0, CHW4)
    unsigned base = blockIdx.y * BSTRIDE + n;

    float4 v[LIF_T];
    // Front-batched independent loads: MLP = 8 LDG.128
    #pragma unroll
    for (int t = 0; t < LIF_T; t++)
        v[t] = x[base + (unsigned)t * CHW4];

    // Phase-align the CTA: all loads issued before any store issues, so the
    // SM's DRAM traffic alternates in 64KB read/write bursts instead of
    // per-warp fine-grained interleaving. BAR cost (~47cyc) hides behind the
    // outstanding load latency.
    __syncthreads();

    float mx = 0.f, my = 0.f, mz = 0.f, mw = 0.f;
    #pragma unroll
    for (int t = 0; t < LIF_T; t++) {
        mx = fmaf(mx, DECAY, v[t].x);
        my = fmaf(my, DECAY, v[t].y);
        mz = fmaf(mz, DECAY, v[t].z);
        mw = fmaf(mw, DECAY, v[t].w);
        float sx = (mx > VTH) ? 1.f : 0.f;
        float sy = (my > VTH) ? 1.f : 0.f;
        float sz = (mz > VTH) ? 1.f : 0.f;
        float sw = (mw > VTH) ? 1.f : 0.f;
        // hard reset where spiked
        mx = (sx != 0.f) ? 0.f : mx;
        my = (sy != 0.f) ? 0.f : my;
        mz = (sz != 0.f) ? 0.f : mz;
        mw = (sw != 0.f) ? 0.f : mw;
        float4 s; s.x = sx; s.y = sy; s.z = sz; s.w = sw;
        out[base + (unsigned)t * CHW4] = s;
    }
}

extern "C" void kernel_launch(void* const* d_in, const int* in_sizes, int n_in,
                              void* d_out, int out_size)
{
    const float4* x = (const float4*)d_in[0];
    float4* out = (float4*)d_out;

    unsigned total   = (unsigned)in_sizes[0];          // B*T*C*H*W
    unsigned batches = total / (LIF_T * CHW4 * 4u);    // = 64 for bench shape

    dim3 grid(CHW4 / TPB, batches, 1);                 // (128, 64) = 8192 CTAs
    lif_scan_kernel<<<grid, TPB>>>(x, out);
}

// round 15
// speedup vs baseline: 1.0034x; 1.0008x over previous
#include <cuda_runtime.h>

// SpikeLayer LIF scan: x [B=64, T=8, C=256, H=32, W=32] f32 -> spikes, same shape.
// mem = mem*0.25 + x; spike = (mem - 0.5) > 0; mem = (1-spike)*mem.
//
// FINAL (converged at HBM ceiling, verified over 10 independent runs at
// 150.0-151.1us kernel / 157.76-158.27us bench):
//   - one thread = 4 neurons (one float4) across all 8 timesteps
//   - LIF recurrence entirely in registers (no spills, regs=32)
//   - front-batched MLP=8 fully-coalesced LDG.128 hides DRAM latency
//   - default cache ops; flat 2D grid (y = batch); 512-thread CTAs
//   - 32-bit index math (CHW4 = 2^16: shifts only)
//
// Complete lever matrix (R1-R14), all neutral or regressions:
//   .cs cache hints (R2), persistent grid-stride (R3, -7%), stride-2 layout
//   (R5, -9%, broken coalescing), coalesced MLP=16 (R6), CTA 256 vs 512 (R7),
//   fused vs trailing stores (R10), intra-CTA load/store phase barrier (R14).
// Every well-formed variant lands at 6.76-6.80 TB/s = 85% of 8 TB/s spec with
// traffic pinned exactly at the 1 GiB floor (512 MiB f32 in + 512 MiB f32
// spikes out, incompressible given output dtype). The residual gap to spec is
// DRAM refresh + read/write bus turnaround on a 50/50 mixed stream -- a
// protocol-level property, not addressable from the kernel.

#define LIF_T 8
#define VTH 0.5f
#define DECAY 0.25f
#define CHW4 65536u                  // C*H*W/4 float4 vectors per (b,t) slice
#define BSTRIDE (CHW4 * 8u)          // float4 vectors per batch sample
#define TPB 512u

__global__ __launch_bounds__(TPB) void lif_scan_kernel(
    const float4* __restrict__ x, float4* __restrict__ out)
{
    unsigned n    = blockIdx.x * TPB + threadIdx.x;    // [0, CHW4)
    unsigned base = blockIdx.y * BSTRIDE + n;

    float4 v[LIF_T];
    // Front-batched independent loads: MLP = 8 LDG.128
    #pragma unroll
    for (int t = 0; t < LIF_T; t++)
        v[t] = x[base + (unsigned)t * CHW4];

    float mx = 0.f, my = 0.f, mz = 0.f, mw = 0.f;
    #pragma unroll
    for (int t = 0; t < LIF_T; t++) {
        mx = fmaf(mx, DECAY, v[t].x);
        my = fmaf(my, DECAY, v[t].y);
        mz = fmaf(mz, DECAY, v[t].z);
        mw = fmaf(mw, DECAY, v[t].w);
        float sx = (mx > VTH) ? 1.f : 0.f;
        float sy = (my > VTH) ? 1.f : 0.f;
        float sz = (mz > VTH) ? 1.f : 0.f;
        float sw = (mw > VTH) ? 1.f : 0.f;
        // hard reset where spiked
        mx = (sx != 0.f) ? 0.f : mx;
        my = (sy != 0.f) ? 0.f : my;
        mz = (sz != 0.f) ? 0.f : mz;
        mw = (sw != 0.f) ? 0.f : mw;
        // store this timestep's spikes (ptxas schedules STGs optimally)
        float4 s; s.x = sx; s.y = sy; s.z = sz; s.w = sw;
        out[base + (unsigned)t * CHW4] = s;
    }
}

extern "C" void kernel_launch(void* const* d_in, const int* in_sizes, int n_in,
                              void* d_out, int out_size)
{
    const float4* x = (const float4*)d_in[0];
    float4* out = (float4*)d_out;

    unsigned total   = (unsigned)in_sizes[0];          // B*T*C*H*W
    unsigned batches = total / (LIF_T * CHW4 * 4u);    // = 64 for bench shape

    dim3 grid(CHW4 / TPB, batches, 1);                 // (128, 64) = 8192 CTAs
    lif_scan_kernel<<<grid, TPB>>>(x, out);
}